// round 6
// baseline (speedup 1.0000x reference)
#include <cuda_runtime.h>
#include <math.h>

#define BATCH 2
#define SEQ   2048
#define CH    1024
#define NH    16
#define HD    128          // per-head dim (2*hd = real||imag)
#define MROWS (BATCH*SEQ)  // 4096

// Scratch (device globals: allocation-free per harness rules)
__device__ __align__(16) float g_Q[(size_t)BATCH*NH*SEQ*HD]; // (b,h,n,d)
__device__ __align__(16) float g_K[(size_t)BATCH*NH*SEQ*HD];
__device__ __align__(16) float g_V[(size_t)BATCH*NH*SEQ*HD];
__device__ __align__(16) float g_O[(size_t)BATCH*SEQ*2*CH];  // (b,n, h*128+d)

// ---------------------------------------------------------------------------
// Classic 128x128 blocked SGEMM, BK=8, 256 threads, 8x8 microtile per thread.
// C = A(M x K) @ B(K x Nc).
// mode 0: QKV fused — blockIdx.z in {0,1,2} selects {B0,B1,B2}={Wq,Wk,Wv} and
//         writes g_Q/g_K/g_V in (b,h,n,d) layout (col tile bn == head).
// mode 1: O-projection — A is g_O, B0=Wo, writes row-major into Cplain.
// All dims divisible by tile sizes (4096 x {2048,1024} x {1024,2048}).
// ---------------------------------------------------------------------------
__global__ void sgemm_kernel(const float* __restrict__ A,
                             const float* __restrict__ B0,
                             const float* __restrict__ B1,
                             const float* __restrict__ B2,
                             float* __restrict__ Cplain,
                             int K, int Nc, int mode)
{
    __shared__ __align__(16) float As[8][132];  // transposed A tile, padded
    __shared__ __align__(16) float Bs[8][128];

    const int tid = threadIdx.x;
    const int tx = tid & 15, ty = tid >> 4;
    const int bm = blockIdx.y, bn = blockIdx.x;
    const int dst = (mode == 1) ? 3 : (int)blockIdx.z;

    const float* Ap = (mode == 1) ? g_O : A;
    const float* Bm = (dst == 0) ? B0 : (dst == 1) ? B1 : (dst == 2) ? B2 : B0;

    float acc[8][8];
#pragma unroll
    for (int i = 0; i < 8; i++)
#pragma unroll
        for (int j = 0; j < 8; j++) acc[i][j] = 0.f;

    const int ar = tid >> 1;         // 0..127  (A row in tile)
    const int ak = (tid & 1) << 2;   // 0 or 4  (A k offset)
    const int br = tid >> 5;         // 0..7    (B row in tile)
    const int bc = (tid & 31) << 2;  // 0..124  (B col offset)

    const float* Arow = Ap + (size_t)(bm * 128 + ar) * K;
    const float* Bcol = Bm + (size_t)bn * 128 + bc;

    for (int kt = 0; kt < K; kt += 8) {
        float4 av = *(const float4*)(Arow + kt + ak);
        float4 bv = *(const float4*)(Bcol + (size_t)(kt + br) * Nc);
        __syncthreads();
        As[ak + 0][ar] = av.x;
        As[ak + 1][ar] = av.y;
        As[ak + 2][ar] = av.z;
        As[ak + 3][ar] = av.w;
        *(float4*)&Bs[br][bc] = bv;
        __syncthreads();
#pragma unroll
        for (int k = 0; k < 8; k++) {
            float4 a0 = *(const float4*)&As[k][ty * 8];
            float4 a1 = *(const float4*)&As[k][ty * 8 + 4];
            float4 b0 = *(const float4*)&Bs[k][tx * 8];
            float4 b1 = *(const float4*)&Bs[k][tx * 8 + 4];
            float a[8] = {a0.x, a0.y, a0.z, a0.w, a1.x, a1.y, a1.z, a1.w};
            float b[8] = {b0.x, b0.y, b0.z, b0.w, b1.x, b1.y, b1.z, b1.w};
#pragma unroll
            for (int i = 0; i < 8; i++)
#pragma unroll
                for (int j = 0; j < 8; j++)
                    acc[i][j] = fmaf(a[i], b[j], acc[i][j]);
        }
    }

    if (dst < 3) {
        // (b,h,n,d) layout; Nc==2048 so col tile bn == head index
        float* dbuf = (dst == 0) ? g_Q : (dst == 1) ? g_K : g_V;
        const int h = bn;
#pragma unroll
        for (int i = 0; i < 8; i++) {
            int m = bm * 128 + ty * 8 + i;
            int b = m >> 11, n = m & 2047;
            float* p = dbuf + (((size_t)(b * NH + h) * SEQ + n) * HD) + tx * 8;
            *(float4*)p       = make_float4(acc[i][0], acc[i][1], acc[i][2], acc[i][3]);
            *(float4*)(p + 4) = make_float4(acc[i][4], acc[i][5], acc[i][6], acc[i][7]);
        }
    } else {
#pragma unroll
        for (int i = 0; i < 8; i++) {
            int m = bm * 128 + ty * 8 + i;
            float* p = Cplain + (size_t)m * Nc + bn * 128 + tx * 8;
            *(float4*)p       = make_float4(acc[i][0], acc[i][1], acc[i][2], acc[i][3]);
            *(float4*)(p + 4) = make_float4(acc[i][4], acc[i][5], acc[i][6], acc[i][7]);
        }
    }
}

// ---------------------------------------------------------------------------
// fp32 flash attention, causal. One CTA per (b,h, 32-row q tile).
// 256 threads as 16x16: thread (ty,tx) owns S[2x2] (rows ty*2+, cols tx*2+)
// and O rows ty*2+{0,1}, cols tx*8..tx*8+7.
// scale = 1/sqrt(64) = 0.125 (NOT 1/sqrt(128)).
// Output written directly to g_O in (b, n, h*128+d) layout for the final GEMM.
// ---------------------------------------------------------------------------
__global__ void attn_kernel()
{
    const int bh = blockIdx.y;
    const int b = bh >> 4, h = bh & 15;
    const float* Qh = g_Q + (size_t)bh * SEQ * HD;
    const float* Kh = g_K + (size_t)bh * SEQ * HD;
    const float* Vh = g_V + (size_t)bh * SEQ * HD;
    const int q0 = blockIdx.x * 32;

    __shared__ __align__(16) float Qs[32][HD];
    __shared__ __align__(16) float KVs[32][HD];
    __shared__ float Ps[32][36];

    const int tid = threadIdx.x, tx = tid & 15, ty = tid >> 4;
    const int r0 = ty * 2;           // local q rows
    const int c0 = tx * 2;           // local k cols (S phase)

    // load Q tile
#pragma unroll
    for (int j = 0; j < 4; j++) {
        int i4 = tid + 256 * j;
        int r = i4 >> 5, c = (i4 & 31) << 2;
        *(float4*)&Qs[r][c] = *(const float4*)&Qh[(size_t)(q0 + r) * HD + c];
    }

    float mrow[2] = {-INFINITY, -INFINITY};
    float lrow[2] = {0.f, 0.f};
    float oacc[2][8] = {};

    const int nkt = (q0 >> 5) + 1;
    for (int kt = 0; kt < nkt; ++kt) {
        const int ks = kt << 5;
        __syncthreads();   // prior O-phase reads of KVs done (also fences Qs on iter 0)
#pragma unroll
        for (int j = 0; j < 4; j++) {
            int i4 = tid + 256 * j;
            int r = i4 >> 5, c = (i4 & 31) << 2;
            *(float4*)&KVs[r][c] = *(const float4*)&Kh[(size_t)(ks + r) * HD + c];
        }
        __syncthreads();

        // S = Q K^T  (2x2 per thread)
        float s00 = 0.f, s01 = 0.f, s10 = 0.f, s11 = 0.f;
#pragma unroll 8
        for (int d = 0; d < HD; d += 4) {
            float4 k0 = *(const float4*)&KVs[c0][d];
            float4 k1 = *(const float4*)&KVs[c0 + 1][d];
            float4 qa = *(const float4*)&Qs[r0][d];
            float4 qb = *(const float4*)&Qs[r0 + 1][d];
            s00 = fmaf(qa.x, k0.x, s00); s00 = fmaf(qa.y, k0.y, s00);
            s00 = fmaf(qa.z, k0.z, s00); s00 = fmaf(qa.w, k0.w, s00);
            s01 = fmaf(qa.x, k1.x, s01); s01 = fmaf(qa.y, k1.y, s01);
            s01 = fmaf(qa.z, k1.z, s01); s01 = fmaf(qa.w, k1.w, s01);
            s10 = fmaf(qb.x, k0.x, s10); s10 = fmaf(qb.y, k0.y, s10);
            s10 = fmaf(qb.z, k0.z, s10); s10 = fmaf(qb.w, k0.w, s10);
            s11 = fmaf(qb.x, k1.x, s11); s11 = fmaf(qb.y, k1.y, s11);
            s11 = fmaf(qb.z, k1.z, s11); s11 = fmaf(qb.w, k1.w, s11);
        }
        float s[2][2] = {{s00 * 0.125f, s01 * 0.125f},
                         {s10 * 0.125f, s11 * 0.125f}};
        if (kt == nkt - 1) {   // only the diagonal tile needs masking
#pragma unroll
            for (int qi = 0; qi < 2; qi++)
#pragma unroll
                for (int kj = 0; kj < 2; kj++)
                    if ((ks + c0 + kj) > (q0 + r0 + qi)) s[qi][kj] = -1e30f;
        }

        // online softmax (row reduction across 16 tx lanes, warp-aligned groups)
#pragma unroll
        for (int qi = 0; qi < 2; qi++) {
            float mx = fmaxf(s[qi][0], s[qi][1]);
#pragma unroll
            for (int off = 8; off >= 1; off >>= 1)
                mx = fmaxf(mx, __shfl_xor_sync(0xffffffffu, mx, off));
            float mn = fmaxf(mrow[qi], mx);
            float f = __expf(mrow[qi] - mn);    // exp(-inf)=0 on first tile
            mrow[qi] = mn;
            float p0 = __expf(s[qi][0] - mn);
            float p1 = __expf(s[qi][1] - mn);
            float rs = p0 + p1;
#pragma unroll
            for (int off = 8; off >= 1; off >>= 1)
                rs += __shfl_xor_sync(0xffffffffu, rs, off);
            lrow[qi] = lrow[qi] * f + rs;
#pragma unroll
            for (int j = 0; j < 8; j++) oacc[qi][j] *= f;
            Ps[r0 + qi][c0]     = p0;
            Ps[r0 + qi][c0 + 1] = p1;
        }
        __syncthreads();  // Ps written, S-phase reads of KVs done

        // load V over K
#pragma unroll
        for (int j = 0; j < 4; j++) {
            int i4 = tid + 256 * j;
            int r = i4 >> 5, c = (i4 & 31) << 2;
            *(float4*)&KVs[r][c] = *(const float4*)&Vh[(size_t)(ks + r) * HD + c];
        }
        __syncthreads();

        // O += P @ V
#pragma unroll 4
        for (int kj = 0; kj < 32; ++kj) {
            float p0 = Ps[r0][kj];
            float p1 = Ps[r0 + 1][kj];
            float4 v0 = *(const float4*)&KVs[kj][tx * 8];
            float4 v1 = *(const float4*)&KVs[kj][tx * 8 + 4];
            oacc[0][0] = fmaf(p0, v0.x, oacc[0][0]);
            oacc[0][1] = fmaf(p0, v0.y, oacc[0][1]);
            oacc[0][2] = fmaf(p0, v0.z, oacc[0][2]);
            oacc[0][3] = fmaf(p0, v0.w, oacc[0][3]);
            oacc[0][4] = fmaf(p0, v1.x, oacc[0][4]);
            oacc[0][5] = fmaf(p0, v1.y, oacc[0][5]);
            oacc[0][6] = fmaf(p0, v1.z, oacc[0][6]);
            oacc[0][7] = fmaf(p0, v1.w, oacc[0][7]);
            oacc[1][0] = fmaf(p1, v0.x, oacc[1][0]);
            oacc[1][1] = fmaf(p1, v0.y, oacc[1][1]);
            oacc[1][2] = fmaf(p1, v0.z, oacc[1][2]);
            oacc[1][3] = fmaf(p1, v0.w, oacc[1][3]);
            oacc[1][4] = fmaf(p1, v1.x, oacc[1][4]);
            oacc[1][5] = fmaf(p1, v1.y, oacc[1][5]);
            oacc[1][6] = fmaf(p1, v1.z, oacc[1][6]);
            oacc[1][7] = fmaf(p1, v1.w, oacc[1][7]);
        }
    }

    // normalize + write to (b, n, h*128+d) layout
#pragma unroll
    for (int qi = 0; qi < 2; qi++) {
        float inv = 1.0f / lrow[qi];
        int n = q0 + r0 + qi;
        float* p = g_O + ((size_t)b * SEQ + n) * (2 * CH) + h * HD + tx * 8;
        *(float4*)p = make_float4(oacc[qi][0] * inv, oacc[qi][1] * inv,
                                  oacc[qi][2] * inv, oacc[qi][3] * inv);
        *(float4*)(p + 4) = make_float4(oacc[qi][4] * inv, oacc[qi][5] * inv,
                                        oacc[qi][6] * inv, oacc[qi][7] * inv);
    }
}

extern "C" void kernel_launch(void* const* d_in, const int* in_sizes, int n_in,
                              void* d_out, int out_size)
{
    const float* x  = (const float*)d_in[0];
    const float* Wq = (const float*)d_in[1];
    const float* Wk = (const float*)d_in[2];
    const float* Wv = (const float*)d_in[3];
    const float* Wo = (const float*)d_in[4];
    float* out = (float*)d_out;

    // QKV projections fused into ONE launch: grid.z picks Wq/Wk/Wv and Q/K/V dst.
    // (4096 x 1024) @ (1024 x 2048), head-transposed epilogue
    dim3 gq(2 * CH / 128, MROWS / 128, 3);  // (16, 32, 3)
    sgemm_kernel<<<gq, 256>>>(x, Wq, Wk, Wv, nullptr, CH, 2 * CH, 0);

    // causal flash attention, 32 q-rows per CTA
    attn_kernel<<<dim3(SEQ / 32, BATCH * NH), 256>>>();

    // output projection: (4096 x 2048) @ (2048 x 1024) -> d_out
    dim3 go(CH / 128, MROWS / 128, 1);      // (8, 32)
    sgemm_kernel<<<go, 256>>>(nullptr, Wo, nullptr, nullptr, out, 2 * CH, CH, 1);
}

// round 11
// speedup vs baseline: 2.5725x; 2.5725x over previous
#include <cuda_runtime.h>
#include <math.h>

#define BATCH 2
#define SEQ   2048
#define CH    1024
#define NH    16
#define HD    128          // per-head dim (2*hd = real||imag)
#define MROWS (BATCH*SEQ)  // 4096

// attention tiling
#define TQ 64
#define TK 64
#define QSTR 132           // padded row stride (floats) for Q/K/V smem tiles
#define PSTR 68            // padded row stride (floats) for P tile
#define ATTN_SMEM ((TQ*QSTR + TK*QSTR + TQ*PSTR) * 4)   // 84992 bytes

// Scratch (device globals: allocation-free per harness rules)
__device__ __align__(16) float g_Q[(size_t)BATCH*NH*SEQ*HD]; // (b,h,n,d)
__device__ __align__(16) float g_K[(size_t)BATCH*NH*SEQ*HD];
__device__ __align__(16) float g_V[(size_t)BATCH*NH*SEQ*HD];
__device__ __align__(16) float g_O[(size_t)BATCH*SEQ*2*CH];  // (b,n, h*128+d)

// ---------------------------------------------------------------------------
// Classic 128x128 blocked SGEMM, BK=8, 256 threads, 8x8 microtile per thread.
// (unchanged from the passing round-6 kernel)
// mode 0: QKV fused — blockIdx.z selects {Wq,Wk,Wv} -> g_Q/g_K/g_V (b,h,n,d).
// mode 1: O-projection — A is g_O, B0=Wo, row-major into Cplain.
// ---------------------------------------------------------------------------
__global__ void sgemm_kernel(const float* __restrict__ A,
                             const float* __restrict__ B0,
                             const float* __restrict__ B1,
                             const float* __restrict__ B2,
                             float* __restrict__ Cplain,
                             int K, int Nc, int mode)
{
    __shared__ __align__(16) float As[8][132];
    __shared__ __align__(16) float Bs[8][128];

    const int tid = threadIdx.x;
    const int tx = tid & 15, ty = tid >> 4;
    const int bm = blockIdx.y, bn = blockIdx.x;
    const int dst = (mode == 1) ? 3 : (int)blockIdx.z;

    const float* Ap = (mode == 1) ? g_O : A;
    const float* Bm = (dst == 0) ? B0 : (dst == 1) ? B1 : (dst == 2) ? B2 : B0;

    float acc[8][8];
#pragma unroll
    for (int i = 0; i < 8; i++)
#pragma unroll
        for (int j = 0; j < 8; j++) acc[i][j] = 0.f;

    const int ar = tid >> 1;
    const int ak = (tid & 1) << 2;
    const int br = tid >> 5;
    const int bc = (tid & 31) << 2;

    const float* Arow = Ap + (size_t)(bm * 128 + ar) * K;
    const float* Bcol = Bm + (size_t)bn * 128 + bc;

    for (int kt = 0; kt < K; kt += 8) {
        float4 av = *(const float4*)(Arow + kt + ak);
        float4 bv = *(const float4*)(Bcol + (size_t)(kt + br) * Nc);
        __syncthreads();
        As[ak + 0][ar] = av.x;
        As[ak + 1][ar] = av.y;
        As[ak + 2][ar] = av.z;
        As[ak + 3][ar] = av.w;
        *(float4*)&Bs[br][bc] = bv;
        __syncthreads();
#pragma unroll
        for (int k = 0; k < 8; k++) {
            float4 a0 = *(const float4*)&As[k][ty * 8];
            float4 a1 = *(const float4*)&As[k][ty * 8 + 4];
            float4 b0 = *(const float4*)&Bs[k][tx * 8];
            float4 b1 = *(const float4*)&Bs[k][tx * 8 + 4];
            float a[8] = {a0.x, a0.y, a0.z, a0.w, a1.x, a1.y, a1.z, a1.w};
            float b[8] = {b0.x, b0.y, b0.z, b0.w, b1.x, b1.y, b1.z, b1.w};
#pragma unroll
            for (int i = 0; i < 8; i++)
#pragma unroll
                for (int j = 0; j < 8; j++)
                    acc[i][j] = fmaf(a[i], b[j], acc[i][j]);
        }
    }

    if (dst < 3) {
        float* dbuf = (dst == 0) ? g_Q : (dst == 1) ? g_K : g_V;
        const int h = bn;
#pragma unroll
        for (int i = 0; i < 8; i++) {
            int m = bm * 128 + ty * 8 + i;
            int b = m >> 11, n = m & 2047;
            float* p = dbuf + (((size_t)(b * NH + h) * SEQ + n) * HD) + tx * 8;
            *(float4*)p       = make_float4(acc[i][0], acc[i][1], acc[i][2], acc[i][3]);
            *(float4*)(p + 4) = make_float4(acc[i][4], acc[i][5], acc[i][6], acc[i][7]);
        }
    } else {
#pragma unroll
        for (int i = 0; i < 8; i++) {
            int m = bm * 128 + ty * 8 + i;
            float* p = Cplain + (size_t)m * Nc + bn * 128 + tx * 8;
            *(float4*)p       = make_float4(acc[i][0], acc[i][1], acc[i][2], acc[i][3]);
            *(float4*)(p + 4) = make_float4(acc[i][4], acc[i][5], acc[i][6], acc[i][7]);
        }
    }
}

// ---------------------------------------------------------------------------
// fp32 flash attention v2, causal. One CTA per (b,h, 64-row q tile).
// 256 threads as 16(ty) x 16(tx). LANE-STRIDED ownership kills LDS conflicts:
//   S microtile 4x4: rows {ty+16i}, cols {tx+16j}
//   O microtile 4x8: rows {ty+16i}, cols tx*8..tx*8+7
// K-fragment loads step 1 row between adjacent tx lanes (132-float stride ->
// 2-phase optimal); Q/P loads broadcast within warp. 2 FMA/LDS-float S-phase.
// scale = 1/sqrt(64) = 0.125. Output -> g_O in (b, n, h*128+d) layout.
// ---------------------------------------------------------------------------
__global__ void __launch_bounds__(256, 2) attn_kernel()
{
    extern __shared__ __align__(16) float smem[];
    float* Qs  = smem;                       // TQ x QSTR
    float* KVs = smem + TQ * QSTR;           // TK x QSTR (K, then reused for V)
    float* Ps  = smem + (TQ + TK) * QSTR;    // TQ x PSTR

    const int bh = blockIdx.y;
    const int b = bh >> 4, h = bh & 15;
    const float* Qh = g_Q + (size_t)bh * SEQ * HD;
    const float* Kh = g_K + (size_t)bh * SEQ * HD;
    const float* Vh = g_V + (size_t)bh * SEQ * HD;
    const int q0 = blockIdx.x * TQ;

    const int tid = threadIdx.x, tx = tid & 15, ty = tid >> 4;

    // load Q tile (64x128), coalesced
#pragma unroll
    for (int j = 0; j < 8; j++) {
        int i4 = tid + 256 * j;
        int r = i4 >> 5, c = (i4 & 31) << 2;
        *(float4*)&Qs[r * QSTR + c] = *(const float4*)&Qh[(size_t)(q0 + r) * HD + c];
    }

    float m[4], l[4], o[4][8];
#pragma unroll
    for (int i = 0; i < 4; i++) {
        m[i] = -1e30f; l[i] = 0.f;
#pragma unroll
        for (int c = 0; c < 8; c++) o[i][c] = 0.f;
    }

    const int nkt = blockIdx.x + 1;   // TQ == TK
    for (int kt = 0; kt < nkt; ++kt) {
        const int ks = kt * TK;
        __syncthreads();   // prior-iter PV reads of KVs/Ps done; Q store (kt=0)
#pragma unroll
        for (int j = 0; j < 8; j++) {
            int i4 = tid + 256 * j;
            int r = i4 >> 5, c = (i4 & 31) << 2;
            *(float4*)&KVs[r * QSTR + c] = *(const float4*)&Kh[(size_t)(ks + r) * HD + c];
        }
        __syncthreads();

        // S = Q K^T : 4x4 per thread
        float s[4][4];
#pragma unroll
        for (int i = 0; i < 4; i++)
#pragma unroll
            for (int j = 0; j < 4; j++) s[i][j] = 0.f;

#pragma unroll 4
        for (int d = 0; d < HD; d += 4) {
            float4 qv[4], kv[4];
#pragma unroll
            for (int i = 0; i < 4; i++)
                qv[i] = *(const float4*)&Qs[(ty + 16 * i) * QSTR + d];
#pragma unroll
            for (int j = 0; j < 4; j++)
                kv[j] = *(const float4*)&KVs[(tx + 16 * j) * QSTR + d];
#pragma unroll
            for (int i = 0; i < 4; i++)
#pragma unroll
                for (int j = 0; j < 4; j++) {
                    s[i][j] = fmaf(qv[i].x, kv[j].x, s[i][j]);
                    s[i][j] = fmaf(qv[i].y, kv[j].y, s[i][j]);
                    s[i][j] = fmaf(qv[i].z, kv[j].z, s[i][j]);
                    s[i][j] = fmaf(qv[i].w, kv[j].w, s[i][j]);
                }
        }

        const bool diag = (kt == nkt - 1);
#pragma unroll
        for (int i = 0; i < 4; i++)
#pragma unroll
            for (int j = 0; j < 4; j++) {
                float v = s[i][j] * 0.125f;
                if (diag && (ks + tx + 16 * j) > (q0 + ty + 16 * i)) v = -1e30f;
                s[i][j] = v;
            }

        // online softmax; rows live on the 16 tx lanes of each warp half
#pragma unroll
        for (int i = 0; i < 4; i++) {
            float mx = fmaxf(fmaxf(s[i][0], s[i][1]), fmaxf(s[i][2], s[i][3]));
#pragma unroll
            for (int off = 8; off >= 1; off >>= 1)
                mx = fmaxf(mx, __shfl_xor_sync(0xffffffffu, mx, off));
            float mn = fmaxf(m[i], mx);
            float f = __expf(m[i] - mn);
            m[i] = mn;
            float rs = 0.f;
#pragma unroll
            for (int j = 0; j < 4; j++) {
                float p = __expf(s[i][j] - mn);
                s[i][j] = p;
                rs += p;
            }
#pragma unroll
            for (int off = 8; off >= 1; off >>= 1)
                rs += __shfl_xor_sync(0xffffffffu, rs, off);
            l[i] = l[i] * f + rs;
#pragma unroll
            for (int c = 0; c < 8; c++) o[i][c] *= f;
#pragma unroll
            for (int j = 0; j < 4; j++)
                Ps[(ty + 16 * i) * PSTR + tx + 16 * j] = s[i][j];
        }
        __syncthreads();   // Ps visible; K reads of KVs done

        // load V over K
#pragma unroll
        for (int j = 0; j < 8; j++) {
            int i4 = tid + 256 * j;
            int r = i4 >> 5, c = (i4 & 31) << 2;
            *(float4*)&KVs[r * QSTR + c] = *(const float4*)&Vh[(size_t)(ks + r) * HD + c];
        }
        __syncthreads();

        // O += P @ V
#pragma unroll 2
        for (int kj = 0; kj < TK; ++kj) {
            float p0 = Ps[(ty +  0) * PSTR + kj];
            float p1 = Ps[(ty + 16) * PSTR + kj];
            float p2 = Ps[(ty + 32) * PSTR + kj];
            float p3 = Ps[(ty + 48) * PSTR + kj];
            float4 v0 = *(const float4*)&KVs[kj * QSTR + tx * 8];
            float4 v1 = *(const float4*)&KVs[kj * QSTR + tx * 8 + 4];
            float pv[4] = {p0, p1, p2, p3};
#pragma unroll
            for (int i = 0; i < 4; i++) {
                o[i][0] = fmaf(pv[i], v0.x, o[i][0]);
                o[i][1] = fmaf(pv[i], v0.y, o[i][1]);
                o[i][2] = fmaf(pv[i], v0.z, o[i][2]);
                o[i][3] = fmaf(pv[i], v0.w, o[i][3]);
                o[i][4] = fmaf(pv[i], v1.x, o[i][4]);
                o[i][5] = fmaf(pv[i], v1.y, o[i][5]);
                o[i][6] = fmaf(pv[i], v1.z, o[i][6]);
                o[i][7] = fmaf(pv[i], v1.w, o[i][7]);
            }
        }
    }

    // normalize + write to (b, n, h*128+d) layout
#pragma unroll
    for (int i = 0; i < 4; i++) {
        float inv = 1.0f / l[i];
        int n = q0 + ty + 16 * i;
        float* p = g_O + ((size_t)b * SEQ + n) * (2 * CH) + h * HD + tx * 8;
        *(float4*)p       = make_float4(o[i][0] * inv, o[i][1] * inv,
                                        o[i][2] * inv, o[i][3] * inv);
        *(float4*)(p + 4) = make_float4(o[i][4] * inv, o[i][5] * inv,
                                        o[i][6] * inv, o[i][7] * inv);
    }
}

extern "C" void kernel_launch(void* const* d_in, const int* in_sizes, int n_in,
                              void* d_out, int out_size)
{
    const float* x  = (const float*)d_in[0];
    const float* Wq = (const float*)d_in[1];
    const float* Wk = (const float*)d_in[2];
    const float* Wv = (const float*)d_in[3];
    const float* Wo = (const float*)d_in[4];
    float* out = (float*)d_out;

    // allow >48KB dynamic smem for attn (idempotent host-side call)
    static int smem_set = 0;
    if (!smem_set) {
        cudaFuncSetAttribute(attn_kernel,
                             cudaFuncAttributeMaxDynamicSharedMemorySize,
                             ATTN_SMEM);
        smem_set = 1;
    }

    // QKV projections fused into ONE launch: grid.z picks Wq/Wk/Wv and dst.
    dim3 gq(2 * CH / 128, MROWS / 128, 3);  // (16, 32, 3)
    sgemm_kernel<<<gq, 256>>>(x, Wq, Wk, Wv, nullptr, CH, 2 * CH, 0);

    // causal flash attention, 64 q-rows per CTA
    attn_kernel<<<dim3(SEQ / TQ, BATCH * NH), 256, ATTN_SMEM>>>();

    // output projection: (4096 x 2048) @ (2048 x 1024) -> d_out
    dim3 go(CH / 128, MROWS / 128, 1);      // (8, 32)
    sgemm_kernel<<<go, 256>>>(nullptr, Wo, nullptr, nullptr, out, 2 * CH, CH, 1);
}

// round 13
// speedup vs baseline: 3.7281x; 1.4492x over previous
#include <cuda_runtime.h>
#include <cuda_bf16.h>
#include <math.h>
#include <stdint.h>

#define BATCH 2
#define SEQ   2048
#define CH    1024
#define NH    16
#define HD    128
#define MROWS (BATCH*SEQ)  // 4096

// attention tiling (unchanged, validated at 2801.8us)
#define TQ 64
#define TK 64
#define QSTR 132
#define PSTR 68
#define ATTN_SMEM ((TQ*QSTR + TK*QSTR + TQ*PSTR) * 4)

// mma GEMM tiling
#define ASTR 72                      // smem row stride in bf16 (144B)
#define GSMEM (4 * 128 * ASTR * 2)   // 4 tiles (Ah,Al,Bh,Bl) = 73728 B

// Scratch (device globals: allocation-free per harness rules)
__device__ __align__(16) float g_Q[(size_t)BATCH*NH*SEQ*HD];
__device__ __align__(16) float g_K[(size_t)BATCH*NH*SEQ*HD];
__device__ __align__(16) float g_V[(size_t)BATCH*NH*SEQ*HD];
__device__ __align__(16) float g_O[(size_t)BATCH*SEQ*2*CH];
__device__ __align__(16) __nv_bfloat16 c_xh[(size_t)MROWS*CH];
__device__ __align__(16) __nv_bfloat16 c_xl[(size_t)MROWS*CH];
__device__ __align__(16) __nv_bfloat16 c_wh[(size_t)3*2*CH*CH];
__device__ __align__(16) __nv_bfloat16 c_wl[(size_t)3*2*CH*CH];
__device__ __align__(16) __nv_bfloat16 c_voh[(size_t)CH*2*CH];
__device__ __align__(16) __nv_bfloat16 c_vol[(size_t)CH*2*CH];
__device__ __align__(16) __nv_bfloat16 c_gh[(size_t)MROWS*2*CH];
__device__ __align__(16) __nv_bfloat16 c_gl[(size_t)MROWS*2*CH];

__device__ __forceinline__ uint32_t smem_u32(const void* p) {
    uint32_t a;
    asm("{ .reg .u64 t; cvta.to.shared.u64 t, %1; cvt.u32.u64 %0, t; }"
        : "=r"(a) : "l"(p));
    return a;
}
__device__ __forceinline__ void ldm_x4(uint32_t* r, uint32_t addr) {
    asm volatile("ldmatrix.sync.aligned.m8n8.x4.shared.b16 {%0,%1,%2,%3}, [%4];"
                 : "=r"(r[0]), "=r"(r[1]), "=r"(r[2]), "=r"(r[3]) : "r"(addr));
}
__device__ __forceinline__ void mma_bf16(float* d, const uint32_t* a, const uint32_t* b) {
    asm volatile(
        "mma.sync.aligned.m16n8k16.row.col.f32.bf16.bf16.f32 "
        "{%0,%1,%2,%3}, {%4,%5,%6,%7}, {%8,%9}, {%0,%1,%2,%3};"
        : "+f"(d[0]), "+f"(d[1]), "+f"(d[2]), "+f"(d[3])
        : "r"(a[0]), "r"(a[1]), "r"(a[2]), "r"(a[3]), "r"(b[0]), "r"(b[1]));
}

// fp32 -> (hi, lo) bf16 split, vec4
__global__ void fsplit(const float* __restrict__ s, __nv_bfloat16* __restrict__ h,
                       __nv_bfloat16* __restrict__ l, int n4)
{
    int i = blockIdx.x * blockDim.x + threadIdx.x;
    if (i >= n4) return;
    float4 v = ((const float4*)s)[i];
    __nv_bfloat16 hx = __float2bfloat16(v.x), hy = __float2bfloat16(v.y);
    __nv_bfloat16 hz = __float2bfloat16(v.z), hw = __float2bfloat16(v.w);
    __nv_bfloat162 ph0; ph0.x = hx; ph0.y = hy;
    __nv_bfloat162 ph1; ph1.x = hz; ph1.y = hw;
    ((__nv_bfloat162*)h)[2*i]   = ph0;
    ((__nv_bfloat162*)h)[2*i+1] = ph1;
    __nv_bfloat162 pl0, pl1;
    pl0.x = __float2bfloat16(v.x - __bfloat162float(hx));
    pl0.y = __float2bfloat16(v.y - __bfloat162float(hy));
    pl1.x = __float2bfloat16(v.z - __bfloat162float(hz));
    pl1.y = __float2bfloat16(v.w - __bfloat162float(hw));
    ((__nv_bfloat162*)l)[2*i]   = pl0;
    ((__nv_bfloat162*)l)[2*i+1] = pl1;
}

// W [Kd,Nd] row-major -> transposed split bf16 [Nd,Kd]; z selects source
__global__ void wsplit_t(const float* __restrict__ W0, const float* __restrict__ W1,
                         const float* __restrict__ W2, int Kd, int Nd,
                         __nv_bfloat16* __restrict__ oh, __nv_bfloat16* __restrict__ ol)
{
    __shared__ float t[32][33];
    const float* W = (blockIdx.z == 0) ? W0 : (blockIdx.z == 1) ? W1 : W2;
    const size_t zoff = (size_t)blockIdx.z * Kd * Nd;
    const int n0 = blockIdx.x * 32, k0 = blockIdx.y * 32;
    const int tid = threadIdx.x, r = tid >> 3, c4 = (tid & 7) << 2;

    float4 v = *(const float4*)&W[(size_t)(k0 + r) * Nd + n0 + c4];
    t[r][c4 + 0] = v.x; t[r][c4 + 1] = v.y; t[r][c4 + 2] = v.z; t[r][c4 + 3] = v.w;
    __syncthreads();
#pragma unroll
    for (int j = 0; j < 4; j++) {
        float x = t[c4 + j][r];
        __nv_bfloat16 h = __float2bfloat16(x);
        size_t idx = zoff + (size_t)(n0 + r) * Kd + k0 + c4 + j;
        oh[idx] = h;
        ol[idx] = __float2bfloat16(x - __bfloat162float(h));
    }
}

// ---------------------------------------------------------------------------
// Split-bf16 GEMM via mma.sync (base PTX — tcgen05 is compute_103a-gated and
// the harness compiles at compute_103). D[128,128] = A[128,K]·B[128,K]^T with
// Ah·Bh + Ah·Bl + Al·Bh, fp32 accum. 8 warps as 2(m)x4(n), 64x32 per warp.
// mode 0: A=x, B=W^T (z: Wq/Wk/Wv), scatter to g_Q/K/V (b,h,n,d).
// mode 1: A=g_O, B=Wo^T, row-major to Cout.
// ---------------------------------------------------------------------------
__global__ void __launch_bounds__(256) gemm_mma(
    const __nv_bfloat16* __restrict__ Ah, const __nv_bfloat16* __restrict__ Al,
    const __nv_bfloat16* __restrict__ Bh, const __nv_bfloat16* __restrict__ Bl,
    float* __restrict__ Cout, int Kdim, int mode)
{
    extern __shared__ __align__(16) char gsm[];
    __nv_bfloat16* sAh = (__nv_bfloat16*)gsm;
    __nv_bfloat16* sAl = sAh + 128 * ASTR;
    __nv_bfloat16* sBh = sAl + 128 * ASTR;
    __nv_bfloat16* sBl = sBh + 128 * ASTR;
    const uint32_t bAh = smem_u32(sAh), bAl = smem_u32(sAl);
    const uint32_t bBh = smem_u32(sBh), bBl = smem_u32(sBl);

    const int tid = threadIdx.x, lane = tid & 31, w = tid >> 5;
    const int wm = (w & 1) * 64, wn = (w >> 1) * 32;
    const int bm = blockIdx.y, bn = blockIdx.x, bz = blockIdx.z;

    if (mode == 0) {
        size_t zo = (size_t)bz * 2 * CH * CH;
        Bh += zo; Bl += zo;
    }

    float acc[4][4][4];
#pragma unroll
    for (int i = 0; i < 4; i++)
#pragma unroll
        for (int j = 0; j < 4; j++)
#pragma unroll
            for (int r = 0; r < 4; r++) acc[i][j][r] = 0.f;

    // ldmatrix per-lane address offsets (bf16 elements)
    const int a_r = (lane & 7) + ((lane & 8) ? 8 : 0);
    const int a_c = (lane & 16) ? 8 : 0;
    const int b_r = (lane & 7) + ((lane & 16) ? 8 : 0);
    const int b_c = (lane & 8) ? 8 : 0;

    const size_t arow0 = (size_t)(bm * 128) * Kdim;
    const size_t brow0 = (size_t)(bn * 128) * Kdim;
    const int lr = tid >> 3, lc = tid & 7;          // load: row, 16B-col

    const int nch = Kdim >> 6;
    for (int kc = 0; kc < nch; kc++) {
        const int koff = kc << 6;
        __syncthreads();
#pragma unroll
        for (int it = 0; it < 4; it++) {
            int r = lr + it * 32;
            size_t ga = arow0 + (size_t)r * Kdim + koff + lc * 8;
            size_t gb = brow0 + (size_t)r * Kdim + koff + lc * 8;
            *(uint4*)(sAh + r * ASTR + lc * 8) = *(const uint4*)(Ah + ga);
            *(uint4*)(sAl + r * ASTR + lc * 8) = *(const uint4*)(Al + ga);
            *(uint4*)(sBh + r * ASTR + lc * 8) = *(const uint4*)(Bh + gb);
            *(uint4*)(sBl + r * ASTR + lc * 8) = *(const uint4*)(Bl + gb);
        }
        __syncthreads();

#pragma unroll
        for (int k16 = 0; k16 < 4; k16++) {
            const int k0 = k16 * 16;
            uint32_t fah[4][4], fal[4][4];
#pragma unroll
            for (int mi = 0; mi < 4; mi++) {
                uint32_t off = ((wm + mi * 16 + a_r) * ASTR + k0 + a_c) * 2;
                ldm_x4(fah[mi], bAh + off);
                ldm_x4(fal[mi], bAl + off);
            }
            uint32_t fbh[2][4], fbl[2][4];
#pragma unroll
            for (int np = 0; np < 2; np++) {
                uint32_t off = ((wn + np * 16 + b_r) * ASTR + k0 + b_c) * 2;
                ldm_x4(fbh[np], bBh + off);
                ldm_x4(fbl[np], bBl + off);
            }
#pragma unroll
            for (int mi = 0; mi < 4; mi++)
#pragma unroll
                for (int nj = 0; nj < 4; nj++) {
                    const uint32_t* bh = &fbh[nj >> 1][(nj & 1) * 2];
                    const uint32_t* bl = &fbl[nj >> 1][(nj & 1) * 2];
                    mma_bf16(acc[mi][nj], fah[mi], bh);
                    mma_bf16(acc[mi][nj], fah[mi], bl);
                    mma_bf16(acc[mi][nj], fal[mi], bh);
                }
        }
    }

    // epilogue: d0,d1 -> (row lane/4, col 2*(lane%4)); d2,d3 -> row+8
    const int er = lane >> 2, ec = (lane & 3) * 2;
#pragma unroll
    for (int mi = 0; mi < 4; mi++)
#pragma unroll
        for (int nj = 0; nj < 4; nj++) {
            float* d = acc[mi][nj];
            int row = wm + mi * 16 + er;
            int col = wn + nj * 8 + ec;
            if (mode == 0) {
                float* dbuf = (bz == 0) ? g_Q : (bz == 1) ? g_K : g_V;
                int m0 = bm * 128 + row;
                int b0 = m0 >> 11, n0 = m0 & 2047;
                float* p0 = dbuf + (((size_t)(b0 * NH + bn) * SEQ + n0) * HD) + col;
                *(float2*)p0 = make_float2(d[0], d[1]);
                int m1 = m0 + 8;
                int b1 = m1 >> 11, n1 = m1 & 2047;
                float* p1 = dbuf + (((size_t)(b1 * NH + bn) * SEQ + n1) * HD) + col;
                *(float2*)p1 = make_float2(d[2], d[3]);
            } else {
                float* p0 = Cout + (size_t)(bm * 128 + row) * CH + bn * 128 + col;
                *(float2*)p0 = make_float2(d[0], d[1]);
                *(float2*)(p0 + 8 * CH) = make_float2(d[2], d[3]);
            }
        }
}

// ---------------------------------------------------------------------------
// fp32 flash attention v2 (unchanged — validated at 2801.8us)
// ---------------------------------------------------------------------------
__global__ void __launch_bounds__(256, 2) attn_kernel()
{
    extern __shared__ __align__(16) float smem[];
    float* Qs  = smem;
    float* KVs = smem + TQ * QSTR;
    float* Ps  = smem + (TQ + TK) * QSTR;

    const int bh = blockIdx.y;
    const int b = bh >> 4, h = bh & 15;
    const float* Qh = g_Q + (size_t)bh * SEQ * HD;
    const float* Kh = g_K + (size_t)bh * SEQ * HD;
    const float* Vh = g_V + (size_t)bh * SEQ * HD;
    const int q0 = blockIdx.x * TQ;

    const int tid = threadIdx.x, tx = tid & 15, ty = tid >> 4;

#pragma unroll
    for (int j = 0; j < 8; j++) {
        int i4 = tid + 256 * j;
        int r = i4 >> 5, c = (i4 & 31) << 2;
        *(float4*)&Qs[r * QSTR + c] = *(const float4*)&Qh[(size_t)(q0 + r) * HD + c];
    }

    float m[4], l[4], o[4][8];
#pragma unroll
    for (int i = 0; i < 4; i++) {
        m[i] = -1e30f; l[i] = 0.f;
#pragma unroll
        for (int c = 0; c < 8; c++) o[i][c] = 0.f;
    }

    const int nkt = blockIdx.x + 1;
    for (int kt = 0; kt < nkt; ++kt) {
        const int ks = kt * TK;
        __syncthreads();
#pragma unroll
        for (int j = 0; j < 8; j++) {
            int i4 = tid + 256 * j;
            int r = i4 >> 5, c = (i4 & 31) << 2;
            *(float4*)&KVs[r * QSTR + c] = *(const float4*)&Kh[(size_t)(ks + r) * HD + c];
        }
        __syncthreads();

        float s[4][4];
#pragma unroll
        for (int i = 0; i < 4; i++)
#pragma unroll
            for (int j = 0; j < 4; j++) s[i][j] = 0.f;

#pragma unroll 4
        for (int d = 0; d < HD; d += 4) {
            float4 qv[4], kv[4];
#pragma unroll
            for (int i = 0; i < 4; i++)
                qv[i] = *(const float4*)&Qs[(ty + 16 * i) * QSTR + d];
#pragma unroll
            for (int j = 0; j < 4; j++)
                kv[j] = *(const float4*)&KVs[(tx + 16 * j) * QSTR + d];
#pragma unroll
            for (int i = 0; i < 4; i++)
#pragma unroll
                for (int j = 0; j < 4; j++) {
                    s[i][j] = fmaf(qv[i].x, kv[j].x, s[i][j]);
                    s[i][j] = fmaf(qv[i].y, kv[j].y, s[i][j]);
                    s[i][j] = fmaf(qv[i].z, kv[j].z, s[i][j]);
                    s[i][j] = fmaf(qv[i].w, kv[j].w, s[i][j]);
                }
        }

        const bool diag = (kt == nkt - 1);
#pragma unroll
        for (int i = 0; i < 4; i++)
#pragma unroll
            for (int j = 0; j < 4; j++) {
                float v = s[i][j] * 0.125f;
                if (diag && (ks + tx + 16 * j) > (q0 + ty + 16 * i)) v = -1e30f;
                s[i][j] = v;
            }

#pragma unroll
        for (int i = 0; i < 4; i++) {
            float mx = fmaxf(fmaxf(s[i][0], s[i][1]), fmaxf(s[i][2], s[i][3]));
#pragma unroll
            for (int off = 8; off >= 1; off >>= 1)
                mx = fmaxf(mx, __shfl_xor_sync(0xffffffffu, mx, off));
            float mn = fmaxf(m[i], mx);
            float f = __expf(m[i] - mn);
            m[i] = mn;
            float rs = 0.f;
#pragma unroll
            for (int j = 0; j < 4; j++) {
                float p = __expf(s[i][j] - mn);
                s[i][j] = p;
                rs += p;
            }
#pragma unroll
            for (int off = 8; off >= 1; off >>= 1)
                rs += __shfl_xor_sync(0xffffffffu, rs, off);
            l[i] = l[i] * f + rs;
#pragma unroll
            for (int c = 0; c < 8; c++) o[i][c] *= f;
#pragma unroll
            for (int j = 0; j < 4; j++)
                Ps[(ty + 16 * i) * PSTR + tx + 16 * j] = s[i][j];
        }
        __syncthreads();

#pragma unroll
        for (int j = 0; j < 8; j++) {
            int i4 = tid + 256 * j;
            int r = i4 >> 5, c = (i4 & 31) << 2;
            *(float4*)&KVs[r * QSTR + c] = *(const float4*)&Vh[(size_t)(ks + r) * HD + c];
        }
        __syncthreads();

#pragma unroll 2
        for (int kj = 0; kj < TK; ++kj) {
            float p0 = Ps[(ty +  0) * PSTR + kj];
            float p1 = Ps[(ty + 16) * PSTR + kj];
            float p2 = Ps[(ty + 32) * PSTR + kj];
            float p3 = Ps[(ty + 48) * PSTR + kj];
            float4 v0 = *(const float4*)&KVs[kj * QSTR + tx * 8];
            float4 v1 = *(const float4*)&KVs[kj * QSTR + tx * 8 + 4];
            float pv[4] = {p0, p1, p2, p3};
#pragma unroll
            for (int i = 0; i < 4; i++) {
                o[i][0] = fmaf(pv[i], v0.x, o[i][0]);
                o[i][1] = fmaf(pv[i], v0.y, o[i][1]);
                o[i][2] = fmaf(pv[i], v0.z, o[i][2]);
                o[i][3] = fmaf(pv[i], v0.w, o[i][3]);
                o[i][4] = fmaf(pv[i], v1.x, o[i][4]);
                o[i][5] = fmaf(pv[i], v1.y, o[i][5]);
                o[i][6] = fmaf(pv[i], v1.z, o[i][6]);
                o[i][7] = fmaf(pv[i], v1.w, o[i][7]);
            }
        }
    }

#pragma unroll
    for (int i = 0; i < 4; i++) {
        float inv = 1.0f / l[i];
        int n = q0 + ty + 16 * i;
        float* p = g_O + ((size_t)b * SEQ + n) * (2 * CH) + h * HD + tx * 8;
        *(float4*)p       = make_float4(o[i][0] * inv, o[i][1] * inv,
                                        o[i][2] * inv, o[i][3] * inv);
        *(float4*)(p + 4) = make_float4(o[i][4] * inv, o[i][5] * inv,
                                        o[i][6] * inv, o[i][7] * inv);
    }
}

extern "C" void kernel_launch(void* const* d_in, const int* in_sizes, int n_in,
                              void* d_out, int out_size)
{
    const float* x  = (const float*)d_in[0];
    const float* Wq = (const float*)d_in[1];
    const float* Wk = (const float*)d_in[2];
    const float* Wv = (const float*)d_in[3];
    const float* Wo = (const float*)d_in[4];
    float* out = (float*)d_out;

    static int attr_set = 0;
    if (!attr_set) {
        cudaFuncSetAttribute(attn_kernel,
                             cudaFuncAttributeMaxDynamicSharedMemorySize, ATTN_SMEM);
        cudaFuncSetAttribute(gemm_mma,
                             cudaFuncAttributeMaxDynamicSharedMemorySize, GSMEM);
        attr_set = 1;
    }

    __nv_bfloat16 *xh, *xl, *wh, *wl, *voh, *vol, *gh, *gl;
    cudaGetSymbolAddress((void**)&xh,  c_xh);
    cudaGetSymbolAddress((void**)&xl,  c_xl);
    cudaGetSymbolAddress((void**)&wh,  c_wh);
    cudaGetSymbolAddress((void**)&wl,  c_wl);
    cudaGetSymbolAddress((void**)&voh, c_voh);
    cudaGetSymbolAddress((void**)&vol, c_vol);
    cudaGetSymbolAddress((void**)&gh,  c_gh);
    cudaGetSymbolAddress((void**)&gl,  c_gl);
    float* gO;
    cudaGetSymbolAddress((void**)&gO, g_O);

    // 1) split-convert x; transpose+split W's
    fsplit<<<(MROWS * CH / 4 + 255) / 256, 256>>>(x, xh, xl, MROWS * CH / 4);
    wsplit_t<<<dim3(2 * CH / 32, CH / 32, 3), 256>>>(Wq, Wk, Wv, CH, 2 * CH, wh, wl);
    wsplit_t<<<dim3(CH / 32, 2 * CH / 32, 1), 256>>>(Wo, Wo, Wo, 2 * CH, CH, voh, vol);

    // 2) QKV via mma.sync tensor cores (z selects W and Q/K/V dst)
    gemm_mma<<<dim3(2 * CH / 128, MROWS / 128, 3), 256, GSMEM>>>(
        xh, xl, wh, wl, nullptr, CH, 0);

    // 3) causal flash attention (unchanged)
    attn_kernel<<<dim3(SEQ / TQ, BATCH * NH), 256, ATTN_SMEM>>>();

    // 4) split-convert attention output; O-projection via mma.sync
    fsplit<<<(MROWS * 2 * CH / 4 + 255) / 256, 256>>>(gO, gh, gl, MROWS * 2 * CH / 4);
    gemm_mma<<<dim3(CH / 128, MROWS / 128, 1), 256, GSMEM>>>(
        gh, gl, voh, vol, out, 2 * CH, 1);
}